// round 16
// baseline (speedup 1.0000x reference)
#include <cuda_runtime.h>
#include <cuda_fp16.h>
#include <cstdint>
#include <math.h>

#define N_NODES  50000
#define N_HEDGES 50000
#define NNZ      800000
#define F_IN     256
#define HID      256
#define F_OUT    128
#define NCHUNK   196   // ceil(50000/256)
#define HALF_N   25000 // node-row chunk for GEMM/gather-v pipelining

// Packed W offsets (uint32 = half2 units, k-paired layout [K/2][N])
#define WP1_OFF  0
#define WP2_OFF  32768          // 128*256
#define WP3_OFF  65536          // + 128*256
#define WP_TOTAL 81920          // + 128*128

// ---------------- scratch (device globals; no allocs allowed) ----------------
__device__ __align__(128) float g_bufA[N_NODES * HID];  // msg (fp16)
__device__ __align__(128) float g_bufB[N_NODES * HID];  // xh / xe (fp16)
__device__ __align__(128) float g_bufC[N_NODES * HID];  // h   (fp16)
__device__ __align__(128) uint32_t g_Wp[WP_TOTAL];      // packed fp16 weights
__device__ __align__(128) float g_inv_v[N_NODES];
__device__ __align__(128) float g_inv_e[N_HEDGES];
__device__ __align__(128) int   g_cnt_v[N_NODES];
__device__ __align__(128) int   g_cnt_e[N_HEDGES];
__device__ __align__(128) int   g_cur_v[N_NODES];
__device__ __align__(128) int   g_cur_e[N_HEDGES];
__device__ __align__(128) int   g_off_v[N_NODES + 1];
__device__ __align__(128) int   g_off_e[N_HEDGES + 1];
__device__ __align__(128) int   g_vi[NNZ];
__device__ __align__(128) int   g_hi[NNZ];
__device__ __align__(128) int   g_nbr_e[NNZ];
__device__ __align__(128) int   g_nbr_v[NNZ];
__device__ __align__(128) int   g_bsum[2 * NCHUNK];
__device__ int g_flag[1];

// ---------------- prep kernels ----------------
__global__ void k_zero_all(const int* __restrict__ ei) {
    int i = blockIdx.x * blockDim.x + threadIdx.x;
    if (i < N_NODES)  { g_cnt_v[i] = 0; g_cur_v[i] = 0; }
    if (i < N_HEDGES) { g_cnt_e[i] = 0; g_cur_e[i] = 0; }
    if (blockIdx.x == 0 && threadIdx.x == 0) {
        int z = 0;
        #pragma unroll
        for (int k = 1; k < 64; k += 2) z |= ei[k];
        g_flag[0] = (z == 0) ? 1 : 0;
    }
}

__global__ void k_convert(const void* __restrict__ ei_raw) {
    int i = blockIdx.x * blockDim.x + threadIdx.x;
    if (i >= NNZ) return;
    int v, h;
    if (g_flag[0]) {
        const long long* e = (const long long*)ei_raw;
        v = (int)e[i];
        h = (int)e[NNZ + i];
    } else {
        const int* e = (const int*)ei_raw;
        v = e[i];
        h = e[NNZ + i];
    }
    g_vi[i] = v;
    g_hi[i] = h;
    atomicAdd(&g_cnt_v[v], 1);
    atomicAdd(&g_cnt_e[h], 1);
}

__device__ __forceinline__ int block_scan_incl(int val, int* warp_sums) {
    int lane = threadIdx.x & 31, w = threadIdx.x >> 5;
    #pragma unroll
    for (int d = 1; d < 32; d <<= 1) {
        int n = __shfl_up_sync(0xffffffffu, val, d);
        if (lane >= d) val += n;
    }
    if (lane == 31) warp_sums[w] = val;
    __syncthreads();
    if (w == 0) {
        int s = (lane < 8) ? warp_sums[lane] : 0;
        #pragma unroll
        for (int d = 1; d < 8; d <<= 1) {
            int n = __shfl_up_sync(0xffffffffu, s, d);
            if (lane >= d) s += n;
        }
        if (lane < 8) warp_sums[lane] = s;
    }
    __syncthreads();
    if (w > 0) val += warp_sums[w - 1];
    return val;
}

// Phase A (per array): block-local exclusive scans + block sums. arr: 0=e, 1=v.
__global__ void k_scanA(int arr) {
    __shared__ int ws[8];
    int idx = blockIdx.x * 256 + threadIdx.x;
    const int* cnt = arr ? g_cnt_v : g_cnt_e;
    int* off       = arr ? g_off_v : g_off_e;
    int val = (idx < 50000) ? cnt[idx] : 0;
    int incl = block_scan_incl(val, ws);
    if (idx < 50000) off[idx] = incl - val;
    if (threadIdx.x == 255) g_bsum[arr * NCHUNK + blockIdx.x] = incl;
}

// Phase C (per array): block base via warp-reduce over earlier block sums;
// adds base, computes inverse degree. off[50000] = NNZ.
__global__ void k_scanC(int arr) {
    __shared__ int sbase;
    int blk = blockIdx.x;
    int idx = blk * 256 + threadIdx.x;
    if (threadIdx.x < 32) {
        int s = 0;
        for (int i = threadIdx.x; i < blk; i += 32) s += g_bsum[arr * NCHUNK + i];
        #pragma unroll
        for (int d = 16; d; d >>= 1) s += __shfl_down_sync(0xffffffffu, s, d);
        if (threadIdx.x == 0) sbase = s;
    }
    __syncthreads();
    int base = sbase;
    if (idx < 50000) {
        if (arr) {
            g_off_v[idx] += base;
            g_inv_v[idx] = 1.0f / (float)max(g_cnt_v[idx], 1);
        } else {
            g_off_e[idx] += base;
            g_inv_e[idx] = 1.0f / (float)max(g_cnt_e[idx], 1);
        }
    }
    if (idx == 49999) (arr ? g_off_v : g_off_e)[50000] = NNZ;
}

__global__ void k_fill_e() {
    int i = blockIdx.x * blockDim.x + threadIdx.x;
    if (i >= NNZ) return;
    int v = g_vi[i], h = g_hi[i];
    int pe = g_off_e[h] + atomicAdd(&g_cur_e[h], 1);
    g_nbr_e[pe] = v;
}

__global__ void k_fill_v() {
    int i = blockIdx.x * blockDim.x + threadIdx.x;
    if (i >= NNZ) return;
    int v = g_vi[i], h = g_hi[i];
    int pv = g_off_v[v] + atomicAdd(&g_cur_v[v], 1);
    g_nbr_v[pv] = h;
}

// ---------------- packing kernels ----------------
__global__ void k_packW(const float* __restrict__ W1, const float* __restrict__ W2,
                        const float* __restrict__ W3) {
    int i = blockIdx.x * blockDim.x + threadIdx.x;
    if (i >= WP_TOTAL) return;
    const float* W; int base, N;
    if (i < WP2_OFF)      { W = W1; base = i;           N = HID;  }
    else if (i < WP3_OFF) { W = W2; base = i - WP2_OFF; N = HID;  }
    else                  { W = W3; base = i - WP3_OFF; N = F_OUT; }
    int k2 = base / N, n = base % N;
    __half2 h = __floats2half2_rn(W[(2 * k2) * N + n], W[(2 * k2 + 1) * N + n]);
    g_Wp[i] = *(uint32_t*)&h;
}

__global__ void k_packX(const float* __restrict__ x, __half* __restrict__ xh) {
    int i = blockIdx.x * blockDim.x + threadIdx.x;
    if (i >= N_NODES * F_IN / 8) return;
    const float4* p = (const float4*)(x + (size_t)i * 8);
    float4 a = p[0], b = p[1];
    uint4 o;
    __half2 h;
    h = __floats2half2_rn(a.x, a.y); o.x = *(uint32_t*)&h;
    h = __floats2half2_rn(a.z, a.w); o.y = *(uint32_t*)&h;
    h = __floats2half2_rn(b.x, b.y); o.z = *(uint32_t*)&h;
    h = __floats2half2_rn(b.z, b.w); o.w = *(uint32_t*)&h;
    ((uint4*)xh)[i] = o;
}

// ---------------- FP16 tensor-core GEMM (fp32 accum), fp16 out --------------
__global__ __launch_bounds__(256, 2)
void k_hgemm(const __half* __restrict__ A, const uint32_t* __restrict__ Bp,
             __half* __restrict__ C, int M, int K, int N) {
    __shared__ uint32_t As2[2][8][132];
    __shared__ uint32_t Bs2[2][8][132];
    const int t = threadIdx.x;
    const int lane = t & 31;
    const int warp = t >> 5;
    const int warp_m = (warp & 1) * 64;
    const int warp_n = (warp >> 1) * 32;
    const int gid = lane >> 2;
    const int tg  = lane & 3;

    const int arow = t >> 1, ak2 = (t & 1) * 4;
    const int bk2 = t >> 5,  bn4 = (t & 31) * 4;

    const int bm = blockIdx.y * 128, bn = blockIdx.x * 128;
    const bool arow_ok = (bm + arow) < M;
    const __half* Ap = A + (size_t)(bm + arow) * K + ak2 * 2;
    const uint32_t* Bpp = Bp + (size_t)bk2 * N + bn + bn4;

    float acc[4][4][4] = {};
    uint4 ah, bw;

    ah = arow_ok ? *(const uint4*)Ap : make_uint4(0, 0, 0, 0);
    bw = *(const uint4*)Bpp;
    As2[0][ak2 + 0][arow] = ah.x;
    As2[0][ak2 + 1][arow] = ah.y;
    As2[0][ak2 + 2][arow] = ah.z;
    As2[0][ak2 + 3][arow] = ah.w;
    Bs2[0][bk2][bn4 + 0] = bw.x;
    Bs2[0][bk2][bn4 + 1] = bw.y;
    Bs2[0][bk2][bn4 + 2] = bw.z;
    Bs2[0][bk2][bn4 + 3] = bw.w;
    __syncthreads();

    const int nk = K >> 4;
    for (int kt = 0; kt < nk; kt++) {
        const int cur = kt & 1, nxt = cur ^ 1;
        if (kt + 1 < nk) {
            ah = arow_ok ? *(const uint4*)(Ap + (kt + 1) * 16) : make_uint4(0, 0, 0, 0);
            bw = *(const uint4*)(Bpp + (size_t)(kt + 1) * 8 * N);
        }

        uint32_t af[4][4], bf[4][2];
        #pragma unroll
        for (int mt = 0; mt < 4; mt++) {
            int r = warp_m + mt * 16 + gid;
            af[mt][0] = As2[cur][tg][r];
            af[mt][1] = As2[cur][tg][r + 8];
            af[mt][2] = As2[cur][tg + 4][r];
            af[mt][3] = As2[cur][tg + 4][r + 8];
        }
        #pragma unroll
        for (int nt = 0; nt < 4; nt++) {
            int c = warp_n + nt * 8 + gid;
            bf[nt][0] = Bs2[cur][tg][c];
            bf[nt][1] = Bs2[cur][tg + 4][c];
        }
        #pragma unroll
        for (int mt = 0; mt < 4; mt++)
            #pragma unroll
            for (int nt = 0; nt < 4; nt++) {
                asm volatile(
                    "mma.sync.aligned.m16n8k16.row.col.f32.f16.f16.f32 "
                    "{%0,%1,%2,%3}, {%4,%5,%6,%7}, {%8,%9}, {%0,%1,%2,%3};"
                    : "+f"(acc[mt][nt][0]), "+f"(acc[mt][nt][1]),
                      "+f"(acc[mt][nt][2]), "+f"(acc[mt][nt][3])
                    : "r"(af[mt][0]), "r"(af[mt][1]), "r"(af[mt][2]), "r"(af[mt][3]),
                      "r"(bf[nt][0]), "r"(bf[nt][1]));
            }

        if (kt + 1 < nk) {
            As2[nxt][ak2 + 0][arow] = ah.x;
            As2[nxt][ak2 + 1][arow] = ah.y;
            As2[nxt][ak2 + 2][arow] = ah.z;
            As2[nxt][ak2 + 3][arow] = ah.w;
            Bs2[nxt][bk2][bn4 + 0] = bw.x;
            Bs2[nxt][bk2][bn4 + 1] = bw.y;
            Bs2[nxt][bk2][bn4 + 2] = bw.z;
            Bs2[nxt][bk2][bn4 + 3] = bw.w;
        }
        __syncthreads();
    }

    #pragma unroll
    for (int mt = 0; mt < 4; mt++) {
        int r0 = bm + warp_m + mt * 16 + gid;
        #pragma unroll
        for (int nt = 0; nt < 4; nt++) {
            int c0 = bn + warp_n + nt * 8 + tg * 2;
            if (r0 < M)
                *(__half2*)&C[(size_t)r0 * N + c0] =
                    __floats2half2_rn(acc[mt][nt][0], acc[mt][nt][1]);
            if (r0 + 8 < M)
                *(__half2*)&C[(size_t)(r0 + 8) * N + c0] =
                    __floats2half2_rn(acc[mt][nt][2], acc[mt][nt][3]);
        }
    }
}

// ---------------- CSR gathers over fp16 rows ----------------
// OUT_MODE: 0 = fp16, no bias (v->e). 1 = fp16 + bias + ELU. 2 = fp32 + bias.
// Processes rows [row_base, row_end).
template<int LPG, int RPB, int OUT_MODE>
__global__ __launch_bounds__(LPG * RPB)
void k_gather(const uint4* __restrict__ src,
              const int* __restrict__ off,
              const int* __restrict__ nbr,
              const float* __restrict__ dscale,
              const float* __restrict__ bias,
              void* __restrict__ dst, int row_base, int row_end) {
    const int group = threadIdx.x / LPG;
    const int lane  = threadIdx.x % LPG;
    const int row = row_base + blockIdx.x * RPB + group;
    if (row >= row_end) return;
    const int s0 = off[row], s1 = off[row + 1];

    float2 acc[4] = {};
    int j = s0;
    for (; j + 1 < s1; j += 2) {
        int n0 = __ldg(&nbr[j]);
        int n1 = __ldg(&nbr[j + 1]);
        uint4 p0 = src[(size_t)n0 * LPG + lane];
        uint4 p1 = src[(size_t)n1 * LPG + lane];
        const __half2* h0 = (const __half2*)&p0;
        const __half2* h1 = (const __half2*)&p1;
        #pragma unroll
        for (int i = 0; i < 4; i++) {
            float2 f = __half22float2(__hadd2(h0[i], h1[i]));
            acc[i].x += f.x;
            acc[i].y += f.y;
        }
    }
    if (j < s1) {
        int n0 = __ldg(&nbr[j]);
        uint4 p0 = src[(size_t)n0 * LPG + lane];
        const __half2* h0 = (const __half2*)&p0;
        #pragma unroll
        for (int i = 0; i < 4; i++) {
            float2 a = __half22float2(h0[i]);
            acc[i].x += a.x;
            acc[i].y += a.y;
        }
    }
    float s = dscale[row];
    float v[8];
    #pragma unroll
    for (int i = 0; i < 4; i++) {
        v[2*i]   = acc[i].x * s;
        v[2*i+1] = acc[i].y * s;
    }
    if (OUT_MODE == 0) {
        uint4 outw;
        __half2* oh = (__half2*)&outw;
        #pragma unroll
        for (int i = 0; i < 4; i++)
            oh[i] = __floats2half2_rn(v[2*i], v[2*i+1]);
        ((uint4*)dst)[(size_t)row * LPG + lane] = outw;
    } else {
        const float* bp = bias + lane * 8;
        #pragma unroll
        for (int i = 0; i < 8; i++) v[i] += bp[i];
        if (OUT_MODE == 1) {
            #pragma unroll
            for (int i = 0; i < 8; i++) v[i] = v[i] > 0.f ? v[i] : expm1f(v[i]);
            uint4 outw;
            __half2* oh = (__half2*)&outw;
            #pragma unroll
            for (int i = 0; i < 4; i++)
                oh[i] = __floats2half2_rn(v[2*i], v[2*i+1]);
            ((uint4*)dst)[(size_t)row * LPG + lane] = outw;
        } else {
            float4* dp = (float4*)dst + (size_t)row * (LPG * 2) + lane * 2;
            dp[0] = make_float4(v[0], v[1], v[2], v[3]);
            dp[1] = make_float4(v[4], v[5], v[6], v[7]);
        }
    }
}

// ---------------- host driver ----------------
static inline int cdiv(int a, int b) { return (a + b - 1) / b; }

extern "C" void kernel_launch(void* const* d_in, const int* in_sizes, int n_in,
                              void* d_out, int out_size) {
    const float* x  = (const float*)d_in[0];
    const void*  ei = d_in[1];
    const float* W1 = (const float*)d_in[3];
    const float* b1 = (const float*)d_in[4];
    const float* W2 = (const float*)d_in[5];
    const float* b2 = (const float*)d_in[6];
    const float* W3 = (const float*)d_in[7];
    const float* b3 = (const float*)d_in[8];

    float *A, *B, *C, *inv_v, *inv_e;
    uint32_t* Wp;
    int *off_v, *off_e, *nbr_v, *nbr_e;
    cudaGetSymbolAddress((void**)&A, g_bufA);
    cudaGetSymbolAddress((void**)&B, g_bufB);
    cudaGetSymbolAddress((void**)&C, g_bufC);
    cudaGetSymbolAddress((void**)&Wp, g_Wp);
    cudaGetSymbolAddress((void**)&inv_v, g_inv_v);
    cudaGetSymbolAddress((void**)&inv_e, g_inv_e);
    cudaGetSymbolAddress((void**)&off_v, g_off_v);
    cudaGetSymbolAddress((void**)&off_e, g_off_e);
    cudaGetSymbolAddress((void**)&nbr_v, g_nbr_v);
    cudaGetSymbolAddress((void**)&nbr_e, g_nbr_e);

    const int TB = 256;

    __half* msg = (__half*)A;
    __half* xh  = (__half*)B;   // layer-1 A operand, later reused as xe
    __half* xe  = (__half*)B;
    __half* h   = (__half*)C;
    float*  out = (float*)d_out;

    // ONE extra stream (proven resource budget) + non-timing events.
    cudaStream_t s2;
    cudaStreamCreateWithFlags(&s2, cudaStreamNonBlocking);
    cudaEvent_t evFork, evConv, evG1, evV;
    cudaEvent_t evA1, evB1, evG2, evA2, evB2, evG3;
    cudaEventCreateWithFlags(&evFork, cudaEventDisableTiming);
    cudaEventCreateWithFlags(&evConv, cudaEventDisableTiming);
    cudaEventCreateWithFlags(&evG1,   cudaEventDisableTiming);
    cudaEventCreateWithFlags(&evV,    cudaEventDisableTiming);
    cudaEventCreateWithFlags(&evA1,   cudaEventDisableTiming);
    cudaEventCreateWithFlags(&evB1,   cudaEventDisableTiming);
    cudaEventCreateWithFlags(&evG2,   cudaEventDisableTiming);
    cudaEventCreateWithFlags(&evA2,   cudaEventDisableTiming);
    cudaEventCreateWithFlags(&evB2,   cudaEventDisableTiming);
    cudaEventCreateWithFlags(&evG3,   cudaEventDisableTiming);

    cudaEventRecord(evFork, 0);
    cudaStreamWaitEvent(s2, evFork, 0);

    // ---- s2: weight/x packing + layer-1 GEMM ----
    k_packW<<<cdiv(WP_TOTAL, TB), TB, 0, s2>>>(W1, W2, W3);
    k_packX<<<cdiv(N_NODES * F_IN / 8, TB), TB, 0, s2>>>(x, xh);
    {
        dim3 gg(HID / 128, cdiv(N_NODES, 128));
        k_hgemm<<<gg, 256, 0, s2>>>(xh, Wp + WP1_OFF, msg, N_NODES, F_IN, HID);
    }
    cudaEventRecord(evG1, s2);

    // ---- stream 0: shared prep ----
    k_zero_all<<<cdiv(N_NODES, TB), TB>>>((const int*)ei);
    k_convert<<<cdiv(NNZ, TB), TB>>>(ei);
    cudaEventRecord(evConv, 0);

    // ---- s2 (continued): v-side CSR chain ----
    cudaStreamWaitEvent(s2, evConv, 0);
    k_scanA<<<NCHUNK, 256, 0, s2>>>(1);
    k_scanC<<<NCHUNK, 256, 0, s2>>>(1);
    k_fill_v<<<cdiv(NNZ, TB), TB, 0, s2>>>();
    cudaEventRecord(evV, s2);

    // ---- stream 0: e-side chain ----
    k_scanA<<<NCHUNK, 256>>>(0);
    k_scanC<<<NCHUNK, 256>>>(0);
    k_fill_e<<<cdiv(NNZ, TB), TB>>>();

    cudaStreamWaitEvent(0, evG1, 0);

    // ---- layer 1: gather-e, then chunked gather-v || GEMM2 ----
    k_gather<32, 8, 0><<<cdiv(N_HEDGES, 8), 256>>>(
        (const uint4*)msg, off_e, nbr_e, inv_e, nullptr, xe, 0, N_HEDGES);
    cudaStreamWaitEvent(0, evV, 0);
    k_gather<32, 8, 1><<<cdiv(HALF_N, 8), 256>>>(
        (const uint4*)xe, off_v, nbr_v, inv_v, b1, h, 0, HALF_N);
    cudaEventRecord(evA1, 0);
    k_gather<32, 8, 1><<<cdiv(N_NODES - HALF_N, 8), 256>>>(
        (const uint4*)xe, off_v, nbr_v, inv_v, b1, h, HALF_N, N_NODES);
    cudaEventRecord(evB1, 0);

    // GEMM2 chunks on s2, overlapping gather-v1 chunk B
    {
        dim3 gg(HID / 128, cdiv(HALF_N, 128));
        cudaStreamWaitEvent(s2, evA1, 0);
        k_hgemm<<<gg, 256, 0, s2>>>(h, Wp + WP2_OFF, msg, HALF_N, HID, HID);
        dim3 gg2(HID / 128, cdiv(N_NODES - HALF_N, 128));
        cudaStreamWaitEvent(s2, evB1, 0);
        k_hgemm<<<gg2, 256, 0, s2>>>(h + (size_t)HALF_N * HID, Wp + WP2_OFF,
                                     msg + (size_t)HALF_N * HID,
                                     N_NODES - HALF_N, HID, HID);
        cudaEventRecord(evG2, s2);
    }

    // ---- layer 2: gather-e, then chunked gather-v || GEMM3 ----
    cudaStreamWaitEvent(0, evG2, 0);
    k_gather<32, 8, 0><<<cdiv(N_HEDGES, 8), 256>>>(
        (const uint4*)msg, off_e, nbr_e, inv_e, nullptr, xe, 0, N_HEDGES);
    k_gather<32, 8, 1><<<cdiv(HALF_N, 8), 256>>>(
        (const uint4*)xe, off_v, nbr_v, inv_v, b2, h, 0, HALF_N);
    cudaEventRecord(evA2, 0);
    k_gather<32, 8, 1><<<cdiv(N_NODES - HALF_N, 8), 256>>>(
        (const uint4*)xe, off_v, nbr_v, inv_v, b2, h, HALF_N, N_NODES);
    cudaEventRecord(evB2, 0);

    {
        dim3 gg(F_OUT / 128, cdiv(HALF_N, 128));
        cudaStreamWaitEvent(s2, evA2, 0);
        k_hgemm<<<gg, 256, 0, s2>>>(h, Wp + WP3_OFF, msg, HALF_N, HID, F_OUT);
        dim3 gg2(F_OUT / 128, cdiv(N_NODES - HALF_N, 128));
        cudaStreamWaitEvent(s2, evB2, 0);
        k_hgemm<<<gg2, 256, 0, s2>>>(h + (size_t)HALF_N * HID, Wp + WP3_OFF,
                                     msg + (size_t)HALF_N * F_OUT,
                                     N_NODES - HALF_N, HID, F_OUT);
        cudaEventRecord(evG3, s2);
    }

    // ---- layer 3 gathers ----
    cudaStreamWaitEvent(0, evG3, 0);
    k_gather<16, 16, 0><<<cdiv(N_HEDGES, 16), 256>>>(
        (const uint4*)msg, off_e, nbr_e, inv_e, nullptr, xe, 0, N_HEDGES);
    k_gather<16, 16, 2><<<cdiv(N_NODES, 16), 256>>>(
        (const uint4*)xe, off_v, nbr_v, inv_v, b3, out, 0, N_NODES);
}

// round 17
// speedup vs baseline: 1.0572x; 1.0572x over previous
#include <cuda_runtime.h>
#include <cuda_fp16.h>
#include <cstdint>
#include <math.h>

#define N_NODES  50000
#define N_HEDGES 50000
#define NNZ      800000
#define F_IN     256
#define HID      256
#define F_OUT    128
#define NCHUNK   196   // ceil(50000/256)

// Packed W offsets (uint32 = half2 units, k-paired layout [K/2][N])
#define WP1_OFF  0
#define WP2_OFF  32768          // 128*256
#define WP3_OFF  65536          // + 128*256
#define WP_TOTAL 81920          // + 128*128

// ---------------- scratch (device globals; no allocs allowed) ----------------
__device__ __align__(128) float g_bufA[N_NODES * HID];  // msg (fp16)
__device__ __align__(128) float g_bufB[N_NODES * HID];  // xh / xe (fp16)
__device__ __align__(128) float g_bufC[N_NODES * HID];  // h   (fp16)
__device__ __align__(128) uint32_t g_Wp[WP_TOTAL];      // packed fp16 weights
__device__ __align__(128) float g_inv_v[N_NODES];
__device__ __align__(128) float g_inv_e[N_HEDGES];
__device__ __align__(128) int   g_cnt_v[N_NODES];
__device__ __align__(128) int   g_cnt_e[N_HEDGES];
__device__ __align__(128) int   g_cur_v[N_NODES];
__device__ __align__(128) int   g_cur_e[N_HEDGES];
__device__ __align__(128) int   g_off_v[N_NODES + 1];
__device__ __align__(128) int   g_off_e[N_HEDGES + 1];
__device__ __align__(128) int   g_vi[NNZ];
__device__ __align__(128) int   g_hi[NNZ];
__device__ __align__(128) int   g_nbr_e[NNZ];
__device__ __align__(128) int   g_nbr_v[NNZ];
__device__ __align__(128) int   g_bsum[2 * NCHUNK];
__device__ int g_flag[1];

// ---------------- prep kernels ----------------
__global__ void k_zero_all(const int* __restrict__ ei) {
    int i = blockIdx.x * blockDim.x + threadIdx.x;
    if (i < N_NODES)  { g_cnt_v[i] = 0; g_cur_v[i] = 0; }
    if (i < N_HEDGES) { g_cnt_e[i] = 0; g_cur_e[i] = 0; }
    if (blockIdx.x == 0 && threadIdx.x == 0) {
        int z = 0;
        #pragma unroll
        for (int k = 1; k < 64; k += 2) z |= ei[k];
        g_flag[0] = (z == 0) ? 1 : 0;
    }
}

__global__ void k_convert(const void* __restrict__ ei_raw) {
    int i = blockIdx.x * blockDim.x + threadIdx.x;
    if (i >= NNZ) return;
    int v, h;
    if (g_flag[0]) {
        const long long* e = (const long long*)ei_raw;
        v = (int)e[i];
        h = (int)e[NNZ + i];
    } else {
        const int* e = (const int*)ei_raw;
        v = e[i];
        h = e[NNZ + i];
    }
    g_vi[i] = v;
    g_hi[i] = h;
    atomicAdd(&g_cnt_v[v], 1);
    atomicAdd(&g_cnt_e[h], 1);
}

__device__ __forceinline__ int block_scan_incl(int val, int* warp_sums) {
    int lane = threadIdx.x & 31, w = threadIdx.x >> 5;
    #pragma unroll
    for (int d = 1; d < 32; d <<= 1) {
        int n = __shfl_up_sync(0xffffffffu, val, d);
        if (lane >= d) val += n;
    }
    if (lane == 31) warp_sums[w] = val;
    __syncthreads();
    if (w == 0) {
        int s = (lane < 8) ? warp_sums[lane] : 0;
        #pragma unroll
        for (int d = 1; d < 8; d <<= 1) {
            int n = __shfl_up_sync(0xffffffffu, s, d);
            if (lane >= d) s += n;
        }
        if (lane < 8) warp_sums[lane] = s;
    }
    __syncthreads();
    if (w > 0) val += warp_sums[w - 1];
    return val;
}

// Phase A (per array): block-local exclusive scans + block sums. arr: 0=e, 1=v.
__global__ void k_scanA(int arr) {
    __shared__ int ws[8];
    int idx = blockIdx.x * 256 + threadIdx.x;
    const int* cnt = arr ? g_cnt_v : g_cnt_e;
    int* off       = arr ? g_off_v : g_off_e;
    int val = (idx < 50000) ? cnt[idx] : 0;
    int incl = block_scan_incl(val, ws);
    if (idx < 50000) off[idx] = incl - val;
    if (threadIdx.x == 255) g_bsum[arr * NCHUNK + blockIdx.x] = incl;
}

// Phase C (per array): block base via warp-reduce over earlier block sums;
// adds base, computes inverse degree. off[50000] = NNZ.
__global__ void k_scanC(int arr) {
    __shared__ int sbase;
    int blk = blockIdx.x;
    int idx = blk * 256 + threadIdx.x;
    if (threadIdx.x < 32) {
        int s = 0;
        for (int i = threadIdx.x; i < blk; i += 32) s += g_bsum[arr * NCHUNK + i];
        #pragma unroll
        for (int d = 16; d; d >>= 1) s += __shfl_down_sync(0xffffffffu, s, d);
        if (threadIdx.x == 0) sbase = s;
    }
    __syncthreads();
    int base = sbase;
    if (idx < 50000) {
        if (arr) {
            g_off_v[idx] += base;
            g_inv_v[idx] = 1.0f / (float)max(g_cnt_v[idx], 1);
        } else {
            g_off_e[idx] += base;
            g_inv_e[idx] = 1.0f / (float)max(g_cnt_e[idx], 1);
        }
    }
    if (idx == 49999) (arr ? g_off_v : g_off_e)[50000] = NNZ;
}

__global__ void k_fill_e() {
    int i = blockIdx.x * blockDim.x + threadIdx.x;
    if (i >= NNZ) return;
    int v = g_vi[i], h = g_hi[i];
    int pe = g_off_e[h] + atomicAdd(&g_cur_e[h], 1);
    g_nbr_e[pe] = v;
}

__global__ void k_fill_v() {
    int i = blockIdx.x * blockDim.x + threadIdx.x;
    if (i >= NNZ) return;
    int v = g_vi[i], h = g_hi[i];
    int pv = g_off_v[v] + atomicAdd(&g_cur_v[v], 1);
    g_nbr_v[pv] = h;
}

// ---------------- packing kernels ----------------
__global__ void k_packW(const float* __restrict__ W1, const float* __restrict__ W2,
                        const float* __restrict__ W3) {
    int i = blockIdx.x * blockDim.x + threadIdx.x;
    if (i >= WP_TOTAL) return;
    const float* W; int base, N;
    if (i < WP2_OFF)      { W = W1; base = i;           N = HID;  }
    else if (i < WP3_OFF) { W = W2; base = i - WP2_OFF; N = HID;  }
    else                  { W = W3; base = i - WP3_OFF; N = F_OUT; }
    int k2 = base / N, n = base % N;
    __half2 h = __floats2half2_rn(W[(2 * k2) * N + n], W[(2 * k2 + 1) * N + n]);
    g_Wp[i] = *(uint32_t*)&h;
}

__global__ void k_packX(const float* __restrict__ x, __half* __restrict__ xh) {
    int i = blockIdx.x * blockDim.x + threadIdx.x;
    if (i >= N_NODES * F_IN / 8) return;
    const float4* p = (const float4*)(x + (size_t)i * 8);
    float4 a = p[0], b = p[1];
    uint4 o;
    __half2 h;
    h = __floats2half2_rn(a.x, a.y); o.x = *(uint32_t*)&h;
    h = __floats2half2_rn(a.z, a.w); o.y = *(uint32_t*)&h;
    h = __floats2half2_rn(b.x, b.y); o.z = *(uint32_t*)&h;
    h = __floats2half2_rn(b.z, b.w); o.w = *(uint32_t*)&h;
    ((uint4*)xh)[i] = o;
}

// ---------------- FP16 tensor-core GEMM (fp32 accum), fp16 out --------------
__global__ __launch_bounds__(256, 2)
void k_hgemm(const __half* __restrict__ A, const uint32_t* __restrict__ Bp,
             __half* __restrict__ C, int M, int K, int N) {
    __shared__ uint32_t As2[2][8][132];
    __shared__ uint32_t Bs2[2][8][132];
    const int t = threadIdx.x;
    const int lane = t & 31;
    const int warp = t >> 5;
    const int warp_m = (warp & 1) * 64;
    const int warp_n = (warp >> 1) * 32;
    const int gid = lane >> 2;
    const int tg  = lane & 3;

    const int arow = t >> 1, ak2 = (t & 1) * 4;
    const int bk2 = t >> 5,  bn4 = (t & 31) * 4;

    const int bm = blockIdx.y * 128, bn = blockIdx.x * 128;
    const bool arow_ok = (bm + arow) < M;
    const __half* Ap = A + (size_t)(bm + arow) * K + ak2 * 2;
    const uint32_t* Bpp = Bp + (size_t)bk2 * N + bn + bn4;

    float acc[4][4][4] = {};
    uint4 ah, bw;

    ah = arow_ok ? *(const uint4*)Ap : make_uint4(0, 0, 0, 0);
    bw = *(const uint4*)Bpp;
    As2[0][ak2 + 0][arow] = ah.x;
    As2[0][ak2 + 1][arow] = ah.y;
    As2[0][ak2 + 2][arow] = ah.z;
    As2[0][ak2 + 3][arow] = ah.w;
    Bs2[0][bk2][bn4 + 0] = bw.x;
    Bs2[0][bk2][bn4 + 1] = bw.y;
    Bs2[0][bk2][bn4 + 2] = bw.z;
    Bs2[0][bk2][bn4 + 3] = bw.w;
    __syncthreads();

    const int nk = K >> 4;
    for (int kt = 0; kt < nk; kt++) {
        const int cur = kt & 1, nxt = cur ^ 1;
        if (kt + 1 < nk) {
            ah = arow_ok ? *(const uint4*)(Ap + (kt + 1) * 16) : make_uint4(0, 0, 0, 0);
            bw = *(const uint4*)(Bpp + (size_t)(kt + 1) * 8 * N);
        }

        uint32_t af[4][4], bf[4][2];
        #pragma unroll
        for (int mt = 0; mt < 4; mt++) {
            int r = warp_m + mt * 16 + gid;
            af[mt][0] = As2[cur][tg][r];
            af[mt][1] = As2[cur][tg][r + 8];
            af[mt][2] = As2[cur][tg + 4][r];
            af[mt][3] = As2[cur][tg + 4][r + 8];
        }
        #pragma unroll
        for (int nt = 0; nt < 4; nt++) {
            int c = warp_n + nt * 8 + gid;
            bf[nt][0] = Bs2[cur][tg][c];
            bf[nt][1] = Bs2[cur][tg + 4][c];
        }
        #pragma unroll
        for (int mt = 0; mt < 4; mt++)
            #pragma unroll
            for (int nt = 0; nt < 4; nt++) {
                asm volatile(
                    "mma.sync.aligned.m16n8k16.row.col.f32.f16.f16.f32 "
                    "{%0,%1,%2,%3}, {%4,%5,%6,%7}, {%8,%9}, {%0,%1,%2,%3};"
                    : "+f"(acc[mt][nt][0]), "+f"(acc[mt][nt][1]),
                      "+f"(acc[mt][nt][2]), "+f"(acc[mt][nt][3])
                    : "r"(af[mt][0]), "r"(af[mt][1]), "r"(af[mt][2]), "r"(af[mt][3]),
                      "r"(bf[nt][0]), "r"(bf[nt][1]));
            }

        if (kt + 1 < nk) {
            As2[nxt][ak2 + 0][arow] = ah.x;
            As2[nxt][ak2 + 1][arow] = ah.y;
            As2[nxt][ak2 + 2][arow] = ah.z;
            As2[nxt][ak2 + 3][arow] = ah.w;
            Bs2[nxt][bk2][bn4 + 0] = bw.x;
            Bs2[nxt][bk2][bn4 + 1] = bw.y;
            Bs2[nxt][bk2][bn4 + 2] = bw.z;
            Bs2[nxt][bk2][bn4 + 3] = bw.w;
        }
        __syncthreads();
    }

    #pragma unroll
    for (int mt = 0; mt < 4; mt++) {
        int r0 = bm + warp_m + mt * 16 + gid;
        #pragma unroll
        for (int nt = 0; nt < 4; nt++) {
            int c0 = bn + warp_n + nt * 8 + tg * 2;
            if (r0 < M)
                *(__half2*)&C[(size_t)r0 * N + c0] =
                    __floats2half2_rn(acc[mt][nt][0], acc[mt][nt][1]);
            if (r0 + 8 < M)
                *(__half2*)&C[(size_t)(r0 + 8) * N + c0] =
                    __floats2half2_rn(acc[mt][nt][2], acc[mt][nt][3]);
        }
    }
}

// ---------------- CSR gathers over fp16 rows ----------------
// OUT_MODE: 0 = fp16, no bias (v->e). 1 = fp16 + bias + ELU. 2 = fp32 + bias.
// Index stream vectorized: peel to even j, then int2 (LDG.64) index loads.
template<int LPG, int RPB, int OUT_MODE>
__global__ __launch_bounds__(LPG * RPB)
void k_gather(const uint4* __restrict__ src,
              const int* __restrict__ off,
              const int* __restrict__ nbr,
              const float* __restrict__ dscale,
              const float* __restrict__ bias,
              void* __restrict__ dst, int nrows) {
    const int group = threadIdx.x / LPG;
    const int lane  = threadIdx.x % LPG;
    const int row = blockIdx.x * RPB + group;
    if (row >= nrows) return;
    const int s0 = off[row], s1 = off[row + 1];

    float2 acc[4] = {};
    int j = s0;

    // peel to 8B alignment
    if ((j & 1) && j < s1) {
        int n0 = __ldg(&nbr[j]);
        uint4 p0 = src[(size_t)n0 * LPG + lane];
        const __half2* h0 = (const __half2*)&p0;
        #pragma unroll
        for (int i = 0; i < 4; i++) {
            float2 a = __half22float2(h0[i]);
            acc[i].x += a.x;
            acc[i].y += a.y;
        }
        j++;
    }
    for (; j + 1 < s1; j += 2) {
        int2 nn = __ldg((const int2*)(nbr + j));
        uint4 p0 = src[(size_t)nn.x * LPG + lane];
        uint4 p1 = src[(size_t)nn.y * LPG + lane];
        const __half2* h0 = (const __half2*)&p0;
        const __half2* h1 = (const __half2*)&p1;
        #pragma unroll
        for (int i = 0; i < 4; i++) {
            float2 f = __half22float2(__hadd2(h0[i], h1[i]));
            acc[i].x += f.x;
            acc[i].y += f.y;
        }
    }
    if (j < s1) {
        int n0 = __ldg(&nbr[j]);
        uint4 p0 = src[(size_t)n0 * LPG + lane];
        const __half2* h0 = (const __half2*)&p0;
        #pragma unroll
        for (int i = 0; i < 4; i++) {
            float2 a = __half22float2(h0[i]);
            acc[i].x += a.x;
            acc[i].y += a.y;
        }
    }
    float s = dscale[row];
    float v[8];
    #pragma unroll
    for (int i = 0; i < 4; i++) {
        v[2*i]   = acc[i].x * s;
        v[2*i+1] = acc[i].y * s;
    }
    if (OUT_MODE == 0) {
        uint4 outw;
        __half2* oh = (__half2*)&outw;
        #pragma unroll
        for (int i = 0; i < 4; i++)
            oh[i] = __floats2half2_rn(v[2*i], v[2*i+1]);
        ((uint4*)dst)[(size_t)row * LPG + lane] = outw;
    } else {
        const float* bp = bias + lane * 8;
        #pragma unroll
        for (int i = 0; i < 8; i++) v[i] += bp[i];
        if (OUT_MODE == 1) {
            #pragma unroll
            for (int i = 0; i < 8; i++) v[i] = v[i] > 0.f ? v[i] : expm1f(v[i]);
            uint4 outw;
            __half2* oh = (__half2*)&outw;
            #pragma unroll
            for (int i = 0; i < 4; i++)
                oh[i] = __floats2half2_rn(v[2*i], v[2*i+1]);
            ((uint4*)dst)[(size_t)row * LPG + lane] = outw;
        } else {
            float4* dp = (float4*)dst + (size_t)row * (LPG * 2) + lane * 2;
            dp[0] = make_float4(v[0], v[1], v[2], v[3]);
            dp[1] = make_float4(v[4], v[5], v[6], v[7]);
        }
    }
}

// ---------------- host driver ----------------
static inline int cdiv(int a, int b) { return (a + b - 1) / b; }

extern "C" void kernel_launch(void* const* d_in, const int* in_sizes, int n_in,
                              void* d_out, int out_size) {
    const float* x  = (const float*)d_in[0];
    const void*  ei = d_in[1];
    const float* W1 = (const float*)d_in[3];
    const float* b1 = (const float*)d_in[4];
    const float* W2 = (const float*)d_in[5];
    const float* b2 = (const float*)d_in[6];
    const float* W3 = (const float*)d_in[7];
    const float* b3 = (const float*)d_in[8];

    float *A, *B, *C, *inv_v, *inv_e;
    uint32_t* Wp;
    int *off_v, *off_e, *nbr_v, *nbr_e;
    cudaGetSymbolAddress((void**)&A, g_bufA);
    cudaGetSymbolAddress((void**)&B, g_bufB);
    cudaGetSymbolAddress((void**)&C, g_bufC);
    cudaGetSymbolAddress((void**)&Wp, g_Wp);
    cudaGetSymbolAddress((void**)&inv_v, g_inv_v);
    cudaGetSymbolAddress((void**)&inv_e, g_inv_e);
    cudaGetSymbolAddress((void**)&off_v, g_off_v);
    cudaGetSymbolAddress((void**)&off_e, g_off_e);
    cudaGetSymbolAddress((void**)&nbr_v, g_nbr_v);
    cudaGetSymbolAddress((void**)&nbr_e, g_nbr_e);

    const int TB = 256;

    __half* msg = (__half*)A;
    __half* xh  = (__half*)B;   // layer-1 A operand, later reused as xe
    __half* xe  = (__half*)B;
    __half* h   = (__half*)C;
    float*  out = (float*)d_out;

    // ONE extra stream (proven resource budget). s2 carries pack + GEMM1,
    // then the v-side CSR chain (hidden under fill_e + gather-e1 on stream 0).
    cudaStream_t s2;
    cudaStreamCreateWithFlags(&s2, cudaStreamNonBlocking);
    cudaEvent_t evFork, evConv, evG1, evV;
    cudaEventCreateWithFlags(&evFork, cudaEventDisableTiming);
    cudaEventCreateWithFlags(&evConv, cudaEventDisableTiming);
    cudaEventCreateWithFlags(&evG1,   cudaEventDisableTiming);
    cudaEventCreateWithFlags(&evV,    cudaEventDisableTiming);

    cudaEventRecord(evFork, 0);
    cudaStreamWaitEvent(s2, evFork, 0);

    // ---- s2: weight/x packing + layer-1 GEMM ----
    k_packW<<<cdiv(WP_TOTAL, TB), TB, 0, s2>>>(W1, W2, W3);
    k_packX<<<cdiv(N_NODES * F_IN / 8, TB), TB, 0, s2>>>(x, xh);
    {
        dim3 gg(HID / 128, cdiv(N_NODES, 128));
        k_hgemm<<<gg, 256, 0, s2>>>(xh, Wp + WP1_OFF, msg, N_NODES, F_IN, HID);
    }
    cudaEventRecord(evG1, s2);

    // ---- stream 0: shared prep ----
    k_zero_all<<<cdiv(N_NODES, TB), TB>>>((const int*)ei);
    k_convert<<<cdiv(NNZ, TB), TB>>>(ei);
    cudaEventRecord(evConv, 0);

    // ---- s2 (continued): v-side CSR chain (needed only by gather-v1) ----
    cudaStreamWaitEvent(s2, evConv, 0);
    k_scanA<<<NCHUNK, 256, 0, s2>>>(1);
    k_scanC<<<NCHUNK, 256, 0, s2>>>(1);
    k_fill_v<<<cdiv(NNZ, TB), TB, 0, s2>>>();
    cudaEventRecord(evV, s2);

    // ---- stream 0: e-side chain ----
    k_scanA<<<NCHUNK, 256>>>(0);
    k_scanC<<<NCHUNK, 256>>>(0);
    k_fill_e<<<cdiv(NNZ, TB), TB>>>();

    cudaStreamWaitEvent(0, evG1, 0);

    // ---- layer 1 gathers ----
    k_gather<32, 8, 0><<<cdiv(N_HEDGES, 8), 256>>>(
        (const uint4*)msg, off_e, nbr_e, inv_e, nullptr, xe, N_HEDGES);
    cudaStreamWaitEvent(0, evV, 0);
    k_gather<32, 8, 1><<<cdiv(N_NODES, 8), 256>>>(
        (const uint4*)xe, off_v, nbr_v, inv_v, b1, h, N_NODES);

    // ---- layer 2 ----
    {
        dim3 gg(HID / 128, cdiv(N_NODES, 128));
        k_hgemm<<<gg, 256>>>(h, Wp + WP2_OFF, msg, N_NODES, HID, HID);
        k_gather<32, 8, 0><<<cdiv(N_HEDGES, 8), 256>>>(
            (const uint4*)msg, off_e, nbr_e, inv_e, nullptr, xe, N_HEDGES);
        k_gather<32, 8, 1><<<cdiv(N_NODES, 8), 256>>>(
            (const uint4*)xe, off_v, nbr_v, inv_v, b2, h, N_NODES);
    }
    // ---- layer 3 ----
    {
        dim3 gg(F_OUT / 128, cdiv(N_NODES, 128));
        k_hgemm<<<gg, 256>>>(h, Wp + WP3_OFF, msg, N_NODES, HID, F_OUT);
        k_gather<16, 16, 0><<<cdiv(N_HEDGES, 16), 256>>>(
            (const uint4*)msg, off_e, nbr_e, inv_e, nullptr, xe, N_HEDGES);
        k_gather<16, 16, 2><<<cdiv(N_NODES, 16), 256>>>(
            (const uint4*)xe, off_v, nbr_v, inv_v, b3, out, N_NODES);
    }
}